// round 6
// baseline (speedup 1.0000x reference)
#include <cuda_runtime.h>
#include <math.h>
#include <stdint.h>

#define N_NODES 50000
#define E_EDGES 200000
#define TOT_E   250000
#define HID     64
#define XD      512
#define PAD     132   // smem row pitch (words): conflict-free frags, 16B-aligned

// ---------------- device scratch --------------------------------------------
__device__ int   g_cnt[N_NODES + 1];
__device__ int   g_cur[N_NODES];
__device__ int   g_srcs[TOT_E];       // CSR entries as COMPACT src indices
__device__ int   g_order[N_NODES];    // compact slot -> node id (mask desc)
__device__ int   g_inv[N_NODES];      // node id -> compact slot
__device__ int   g_histp[196][4];     // per-block mask histograms
__device__ int   g_nact[4];
__device__ float g_h0[N_NODES * HID];
__device__ float g_h[N_NODES * HID];
__device__ float g_xlr[(size_t)(N_NODES + 128) * XD];   // compact-indexed
__device__ float g_Wp[128 * XD];      // [Wl|Wr] rows, tf32-truncated (t>0)
__device__ float g_Wsum[64 * XD];     // Wc1+Wc2 truncated (t=0, K=64)
__device__ float g_biasC[XD];
__device__ float g_bias2[HID];

__device__ __forceinline__ float t32(float v) {
    uint32_t u; asm("cvt.rna.tf32.f32 %0, %1;" : "=r"(u) : "f"(v));
    return __uint_as_float(u);
}

// ---------------- L0: fused h0 / weight-prep / Wsum / cnt-init+hist ----------
#define L0_H0   12500
#define L0_PB   (L0_H0 + 256)
#define L0_WS   (L0_PB + 128)
#define L0_GRID (L0_WS + 196)

__global__ void k_l0(const float* __restrict__ feat, const float* __restrict__ W_in,
                     const float* __restrict__ b_in,
                     const float* __restrict__ Wl, const float* __restrict__ Wr,
                     const float* __restrict__ bl, const float* __restrict__ br,
                     const float* __restrict__ bconv, const int* __restrict__ mask) {
    __shared__ float Ws[32 * 64];
    __shared__ float fs[4][32];
    __shared__ int sh[4];
    int b = blockIdx.x, tid = threadIdx.x;
    if (b < L0_H0) {
        // h0 = feat @ W_in + b_in (tf32-truncated), h = h0
        for (int i = tid; i < 32 * 64; i += 256) Ws[i] = W_in[i];
        if (tid < 128) {
            int r = b * 4 + (tid >> 5);
            fs[tid >> 5][tid & 31] = (r < N_NODES) ? feat[r * 32 + (tid & 31)] : 0.f;
        }
        __syncthreads();
        int ty = tid >> 6, c = tid & 63;
        int r = b * 4 + ty;
        if (r >= N_NODES) return;
        float s = b_in[c];
#pragma unroll
        for (int k = 0; k < 32; k++) s += fs[ty][k] * Ws[k * 64 + c];
        float sv = t32(s);
        g_h0[r * 64 + c] = sv;
        g_h[r * 64 + c] = sv;
    } else if (b < L0_PB) {
        int idx = (b - L0_H0) * 256 + tid;     // < 65536
        int k = idx >> 9, j = idx & 511;
        float v = (j < 256) ? Wl[k * 256 + j] : Wr[k * 256 + (j - 256)];
        g_Wp[idx] = t32(v);
        if (idx < XD) g_biasC[idx] = (idx < 256) ? bl[idx] : br[idx - 256];
        if (idx < HID)
            g_bias2[idx] = bconv[idx] + bconv[64 + idx] + bconv[128 + idx] + bconv[192 + idx];
    } else if (b < L0_WS) {
        int idx = (b - L0_PB) * 256 + tid;     // < 32768
        int k = idx >> 9, j = idx & 511;
        float v;
        if (j < 256) v = Wl[k * 256 + j] + Wl[(k + 64) * 256 + j];
        else         v = Wr[k * 256 + (j - 256)] + Wr[(k + 64) * 256 + (j - 256)];
        g_Wsum[idx] = t32(v);
    } else {
        int hb = b - L0_WS;                    // 0..195
        if (tid < 4) sh[tid] = 0;
        __syncthreads();
        int i = hb * 256 + tid;
        if (i < N_NODES) {
            g_cnt[i] = 1;                      // self loop
            int m = mask[i]; m = m < 0 ? 0 : (m > 3 ? 3 : m);
            atomicAdd(&sh[m], 1);
        }
        __syncthreads();
        if (tid < 4) g_histp[hb][tid] = sh[tid];   // overwrite, no zeroing needed
    }
}

// ---------------- count incoming edges ---------------------------------------
__global__ void k_count(const int* __restrict__ ei) {
    int e = blockIdx.x * blockDim.x + threadIdx.x;
    if (e < E_EDGES) atomicAdd(&g_cnt[ei[E_EDGES + e]], 1);
}

// ---------------- fused scan + bucket scatter (1 block) ----------------------
__global__ void k_scansc(const int* __restrict__ mask) {
    __shared__ int wsum[32];
    __shared__ int cur4[4];
    int tid = threadIdx.x, lane = tid & 31, wid = tid >> 5;
    if (tid < 4) cur4[tid] = 0;
    __syncthreads();
    if (tid < 784) atomicAdd(&cur4[tid & 3], g_histp[tid >> 2][tid & 3]);
    __syncthreads();
    if (tid == 0) {
        int h1 = cur4[1], h2 = cur4[2], h3 = cur4[3];
        cur4[3] = 0; cur4[2] = h3; cur4[1] = h3 + h2; cur4[0] = h3 + h2 + h1;
        g_nact[0] = h3 + h2 + h1; g_nact[1] = h3 + h2; g_nact[2] = h3; g_nact[3] = 0;
    }
    __syncthreads();
    int carry = 0;
    for (int base = 0; base < N_NODES; base += 1024) {
        int i = base + tid;
        bool act = (i < N_NODES);
        int v = act ? g_cnt[i] : 0;
        int sv = v;
#pragma unroll
        for (int d = 1; d < 32; d <<= 1) {
            int u = __shfl_up_sync(0xffffffffu, sv, d);
            if (lane >= d) sv += u;
        }
        if (lane == 31) wsum[wid] = sv;
        __syncthreads();
        if (wid == 0) {
            int w = wsum[lane];
#pragma unroll
            for (int d = 1; d < 32; d <<= 1) {
                int u = __shfl_up_sync(0xffffffffu, w, d);
                if (lane >= d) w += u;
            }
            wsum[lane] = w;
        }
        __syncthreads();
        int add = (wid > 0) ? wsum[wid - 1] : 0;
        int incl = sv + add + carry;
        int beg = incl - v;
        // warp-aggregated bucket allocation
        int m = 0;
        if (act) { m = mask[i]; m = m < 0 ? 0 : (m > 3 ? 3 : m); }
        unsigned b0 = __ballot_sync(0xffffffffu, act && m == 0);
        unsigned b1 = __ballot_sync(0xffffffffu, act && m == 1);
        unsigned b2 = __ballot_sync(0xffffffffu, act && m == 2);
        unsigned b3 = __ballot_sync(0xffffffffu, act && m == 3);
        unsigned mym = (m == 0) ? b0 : (m == 1) ? b1 : (m == 2) ? b2 : b3;
        if (!act) mym = 1u;                       // harmless: leader=0
        int rank = __popc(mym & ((1u << lane) - 1));
        int leader = __ffs(mym) - 1;
        int basep = 0;
        if (act && lane == leader) basep = atomicAdd(&cur4[m], __popc(mym));
        basep = __shfl_sync(0xffffffffu, basep, leader);
        if (act) {
            int pos = basep + rank;
            g_order[pos] = i;
            g_inv[i] = pos;
            g_cnt[i] = incl;
            g_srcs[beg] = pos;                    // self loop first (compact id)
            g_cur[i] = beg + 1;
        }
        int total = wsum[31];
        __syncthreads();
        carry += total;
    }
}

// ---------------- fill CSR with compact src ids ------------------------------
__global__ void k_fill(const int* __restrict__ ei) {
    int e = blockIdx.x * blockDim.x + threadIdx.x;
    if (e >= E_EDGES) return;
    int d = ei[E_EDGES + e];
    int p = atomicAdd(&g_cur[d], 1);
    g_srcs[p] = g_inv[ei[e]];
}

// ---------------- HMMA tf32 GEMM, cp.async double-buffered A ----------------
// xlr[compact,512] = A @ W + biasC, A = [h|h0] (K=128) or h (K=64, Wsum).
// grid (4 colblocks, 37) persistent; block 256 = 8 warps (2M x 4N); tile 128x128.
#define GEMM_SMEM (3 * 128 * PAD * 4)

template<int KS>
__device__ __forceinline__ void gemm_main(const uint32_t* __restrict__ aBase,
                                          const uint32_t* __restrict__ bBase,
                                          float acc[4][4][4]) {
#pragma unroll
    for (int mf = 0; mf < 4; mf++)
#pragma unroll
        for (int nf = 0; nf < 4; nf++)
#pragma unroll
            for (int q = 0; q < 4; q++) acc[mf][nf][q] = 0.f;
#pragma unroll 4
    for (int k0 = 0; k0 < KS; k0++) {
        uint32_t a[4][4], b[4][2];
#pragma unroll
        for (int mf = 0; mf < 4; mf++) {
            const uint32_t* ap = aBase + mf * 16 * PAD + k0 * 8;
            a[mf][0] = ap[0];
            a[mf][1] = ap[8 * PAD];
            a[mf][2] = ap[4];
            a[mf][3] = ap[8 * PAD + 4];
        }
#pragma unroll
        for (int nf = 0; nf < 4; nf++) {
            const uint32_t* bp = bBase + k0 * 8 * PAD + nf * 8;
            b[nf][0] = bp[0];
            b[nf][1] = bp[4 * PAD];
        }
#pragma unroll
        for (int mf = 0; mf < 4; mf++)
#pragma unroll
            for (int nf = 0; nf < 4; nf++) {
                asm volatile(
                    "mma.sync.aligned.m16n8k8.row.col.f32.tf32.tf32.f32 "
                    "{%0,%1,%2,%3}, {%4,%5,%6,%7}, {%8,%9}, {%0,%1,%2,%3};"
                    : "+f"(acc[mf][nf][0]), "+f"(acc[mf][nf][1]),
                      "+f"(acc[mf][nf][2]), "+f"(acc[mf][nf][3])
                    : "r"(a[mf][0]), "r"(a[mf][1]), "r"(a[mf][2]), "r"(a[mf][3]),
                      "r"(b[nf][0]), "r"(b[nf][1]));
            }
    }
}

__global__ __launch_bounds__(256, 1) void k_gemm_mma(int tsel, int kd) {
    extern __shared__ uint32_t smg[];
    uint32_t* Bs = smg + 2 * 128 * PAD;
    int nact = g_nact[tsel];
    int ntile = (nact + 127) >> 7;
    int colB = blockIdx.x * 128;
    int tid = threadIdx.x, lane = tid & 31, wid = tid >> 5;
    int mwarp = wid >> 2, nwarp = wid & 3;
    int group = lane >> 2, tig = lane & 3;
    const float* W = (kd == 128) ? g_Wp : g_Wsum;

    // B tile once per CTA (kd rows x 128 cols)
    for (int i = tid; i < kd * 32; i += 256) {
        int k = i >> 5, c4 = (i & 31) * 4;
        float4 v = *(const float4*)&W[k * 512 + colB + c4];
        uint32_t* d = &Bs[k * PAD + c4];
        d[0] = __float_as_uint(v.x); d[1] = __float_as_uint(v.y);
        d[2] = __float_as_uint(v.z); d[3] = __float_as_uint(v.w);
    }

    float2 bia[4];
#pragma unroll
    for (int nf = 0; nf < 4; nf++)
        bia[nf] = *(const float2*)&g_biasC[colB + nwarp * 32 + nf * 8 + 2 * tig];

    uint32_t sb;
    asm("{ .reg .u64 t; cvta.to.shared.u64 t, %1; cvt.u32.u64 %0, t; }" : "=r"(sb) : "l"(smg));

    int m_st = tid >> 1, which = tid & 1;
    int khalf = kd >> 1, n4 = kd >> 3;

    auto stage = [&](int t, int bsel) {
        int r = (t << 7) + m_st;
        bool valid = r < nact;
        int gr = valid ? g_order[r] : 0;
        const float* src = (kd == 128) ? (which ? g_h0 : g_h) : g_h;
        const float* sp = &src[(size_t)gr * 64 + ((kd == 128) ? 0 : which * 32)];
        uint32_t dst = sb + (uint32_t)(bsel * 128 * PAD + m_st * PAD + which * khalf) * 4;
        int sz = valid ? 16 : 0;
        for (int i = 0; i < n4; i++)
            asm volatile("cp.async.ca.shared.global [%0], [%1], 16, %2;"
                         :: "r"(dst + i * 16), "l"(sp + i * 4), "r"(sz) : "memory");
    };

    int tile = blockIdx.y;
    if (tile < ntile) stage(tile, 0);
    asm volatile("cp.async.commit_group;" ::: "memory");
    int buf = 0;
    for (; tile < ntile; tile += gridDim.y) {
        int nxt = tile + gridDim.y;
        if (nxt < ntile) stage(nxt, buf ^ 1);
        asm volatile("cp.async.commit_group;" ::: "memory");
        asm volatile("cp.async.wait_group 1;" ::: "memory");
        __syncthreads();                      // As[buf] + Bs visible to all

        const uint32_t* As = smg + buf * 128 * PAD;
        const uint32_t* aBase = &As[(mwarp * 64 + group) * PAD + tig];
        const uint32_t* bBase = &Bs[tig * PAD + nwarp * 32 + group];
        float acc[4][4][4];
        if (kd == 128) gemm_main<16>(aBase, bBase, acc);
        else           gemm_main<8>(aBase, bBase, acc);
        __syncthreads();                      // done reading As[buf]

        int row0 = tile << 7;
#pragma unroll
        for (int mf = 0; mf < 4; mf++) {
            int r0 = row0 + mwarp * 64 + mf * 16 + group;
#pragma unroll
            for (int nf = 0; nf < 4; nf++) {
                int c = colB + nwarp * 32 + nf * 8 + 2 * tig;
                if (r0 < nact) {
                    float2 v = make_float2(acc[mf][nf][0] + bia[nf].x,
                                           acc[mf][nf][1] + bia[nf].y);
                    *(float2*)&g_xlr[(size_t)r0 * XD + c] = v;
                }
                if (r0 + 8 < nact) {
                    float2 v = make_float2(acc[mf][nf][2] + bia[nf].x,
                                           acc[mf][nf][3] + bia[nf].y);
                    *(float2*)&g_xlr[(size_t)(r0 + 8) * XD + c] = v;
                }
            }
        }
        buf ^= 1;
    }
}

// ---------------- edge kernel: one warp per compact active dst ---------------
__global__ void k_edge(const float* __restrict__ att, int t) {
    int w = (blockIdx.x * blockDim.x + threadIdx.x) >> 5;
    int lane = threadIdx.x & 31;
    int na = g_nact[t];
    if (w >= na) return;
    int norig = g_order[w];

    int j0 = lane * 8;
    const float4 at0 = *(const float4*)&att[j0];
    const float4 at1 = *(const float4*)&att[j0 + 4];
    const float* xrp = &g_xlr[(size_t)w * XD + 256 + j0];
    const float4 xr0 = *(const float4*)xrp;
    const float4 xr1 = *(const float4*)(xrp + 4);

    float acc[8];
#pragma unroll
    for (int i = 0; i < 8; i++) acc[i] = 0.f;
    float den = 0.f;

    int beg = (norig == 0) ? 0 : g_cnt[norig - 1];
    int end = g_cnt[norig];
    for (int e = beg; e < end; e++) {
        int cs = g_srcs[e];
        if (cs >= na) continue;            // src inactive at step t
        const float* xp = &g_xlr[(size_t)cs * XD + j0];
        const float4 x0 = *(const float4*)xp;
        const float4 x1 = *(const float4*)(xp + 4);
        float p, v;
        v = x0.x + xr0.x; v = v > 0.f ? v : 0.2f * v; p  = v * at0.x;
        v = x0.y + xr0.y; v = v > 0.f ? v : 0.2f * v; p += v * at0.y;
        v = x0.z + xr0.z; v = v > 0.f ? v : 0.2f * v; p += v * at0.z;
        v = x0.w + xr0.w; v = v > 0.f ? v : 0.2f * v; p += v * at0.w;
        v = x1.x + xr1.x; v = v > 0.f ? v : 0.2f * v; p += v * at1.x;
        v = x1.y + xr1.y; v = v > 0.f ? v : 0.2f * v; p += v * at1.y;
        v = x1.z + xr1.z; v = v > 0.f ? v : 0.2f * v; p += v * at1.z;
        v = x1.w + xr1.w; v = v > 0.f ? v : 0.2f * v; p += v * at1.w;
        p += __shfl_xor_sync(0xffffffffu, p, 1);
        p += __shfl_xor_sync(0xffffffffu, p, 2);
        p += __shfl_xor_sync(0xffffffffu, p, 4);
        float ex = __expf(p);              // softmax shift-invariant
        den += ex;
        acc[0] += ex * x0.x; acc[1] += ex * x0.y;
        acc[2] += ex * x0.z; acc[3] += ex * x0.w;
        acc[4] += ex * x1.x; acc[5] += ex * x1.y;
        acc[6] += ex * x1.z; acc[7] += ex * x1.w;
    }

    float rden = 1.f / fmaxf(den, 1e-16f);
    float vres[8];
#pragma unroll
    for (int i = 0; i < 8; i++) {
        float v = acc[i] * rden;
        v += __shfl_xor_sync(0xffffffffu, v, 8);
        v += __shfl_xor_sync(0xffffffffu, v, 16);
        vres[i] = v;
    }
    if (lane < 8) {
#pragma unroll
        for (int i = 0; i < 8; i++) {
            int c = lane * 8 + i;
            g_h[norig * 64 + c] = t32(tanhf(vres[i] + g_bias2[c]));
        }
    }
}

// ---------------- out = (h @ Wg + bg) * (current_state > 0) -----------------
__global__ void k_out(const float* __restrict__ Wg, const float* __restrict__ bg,
                      const int* __restrict__ cs, float* __restrict__ out) {
    __shared__ float Ws[64 * 32];
    __shared__ float hs[8][64];
    int tid = threadIdx.x;
    for (int i = tid; i < 64 * 32; i += 256) Ws[i] = Wg[i];
    for (int i = tid; i < 8 * 64; i += 256) {
        int r = blockIdx.x * 8 + (i >> 6);
        hs[i >> 6][i & 63] = (r < N_NODES) ? g_h[r * 64 + (i & 63)] : 0.f;
    }
    __syncthreads();
    int ty = tid >> 5;
    int c = tid & 31;
    int r = blockIdx.x * 8 + ty;
    if (r >= N_NODES) return;
    float s = bg[c];
#pragma unroll
    for (int k = 0; k < 64; k++) s += hs[ty][k] * Ws[k * 32 + c];
    out[r * 32 + c] = (cs[r] > 0) ? s : 0.f;
}

// ---------------- launch -----------------------------------------------------
extern "C" void kernel_launch(void* const* d_in, const int* in_sizes, int n_in,
                              void* d_out, int out_size) {
    const float* feat  = (const float*)d_in[0];
    const float* W_in  = (const float*)d_in[1];
    const float* b_in  = (const float*)d_in[2];
    const float* Wl    = (const float*)d_in[3];
    const float* bl    = (const float*)d_in[4];
    const float* Wr    = (const float*)d_in[5];
    const float* br    = (const float*)d_in[6];
    const float* att   = (const float*)d_in[7];
    const float* bconv = (const float*)d_in[8];
    const float* Wg    = (const float*)d_in[9];
    const float* bg    = (const float*)d_in[10];
    const int*   ei    = (const int*)d_in[11];
    const int*   mask  = (const int*)d_in[12];
    const int*   cstat = (const int*)d_in[13];
    float* out = (float*)d_out;

    cudaFuncSetAttribute(k_gemm_mma, cudaFuncAttributeMaxDynamicSharedMemorySize, GEMM_SMEM);

    k_l0<<<L0_GRID, 256>>>(feat, W_in, b_in, Wl, Wr, bl, br, bconv, mask);   // 0
    k_count<<<(E_EDGES + 255) / 256, 256>>>(ei);                              // 1
    k_scansc<<<1, 1024>>>(mask);                                              // 2
    k_gemm_mma<<<dim3(4, 37), 256, GEMM_SMEM>>>(0, 64);                       // 3 <- ncu
    k_fill<<<(E_EDGES + 255) / 256, 256>>>(ei);                               // 4
    k_edge<<<(N_NODES * 32) / 256, 256>>>(att, 0);                            // 5
    k_gemm_mma<<<dim3(4, 37), 256, GEMM_SMEM>>>(1, 128);                      // 6
    k_edge<<<(N_NODES * 32) / 256, 256>>>(att, 1);                            // 7
    k_gemm_mma<<<dim3(4, 37), 256, GEMM_SMEM>>>(2, 128);                      // 8
    k_edge<<<(N_NODES * 32) / 256, 256>>>(att, 2);                            // 9
    k_out<<<(N_NODES + 7) / 8, 256>>>(Wg, bg, cstat, out);                    // 10
}